// round 12
// baseline (speedup 1.0000x reference)
#include <cuda_runtime.h>
#include <cuda_fp16.h>
#include <math.h>
#include <stdint.h>

// ---------------- problem constants ----------------
#define BATCH    256
#define NREG     36
#define NWORD    60
#define IMG_DIM  2048
#define WORD_DIM 300
#define KPAD_TXT 320
#define EMBED    1024
#define LAMBDA_SM 9.0f
#define M_IMG (BATCH*NREG)     // 9216
#define M_CAP (BATCH*NWORD)    // 15360

// ---------------- scratch (device globals; no allocation allowed) ----------------
__device__ __align__(256) __half g_img_embs[M_IMG * EMBED];
__device__ __align__(256) __half g_cap_embs[M_CAP * EMBED];

__device__ __align__(256) __half g_A16_img[M_IMG * IMG_DIM];
__device__ __align__(256) __half g_A16_cap[M_CAP * KPAD_TXT];
__device__ __align__(256) __half g_W16_img[IMG_DIM * EMBED];
__device__ __align__(256) __half g_W16_txt[KPAD_TXT * EMBED];

// ---------------- PTX helpers (sm_80-level only) ----------------
__device__ __forceinline__ uint32_t s2u(const void* p) {
    uint32_t a;
    asm("{ .reg .u64 t; cvta.to.shared.u64 t, %1; cvt.u32.u64 %0, t; }" : "=r"(a) : "l"(p));
    return a;
}
__device__ __forceinline__ void cp16(uint32_t s, const void* g) {
    asm volatile("cp.async.cg.shared.global [%0], [%1], 16;" :: "r"(s), "l"(g));
}
#define CP_COMMIT() asm volatile("cp.async.commit_group;" ::: "memory")

#define LDSM_X4(r0, r1, r2, r3, addr)                                            \
    asm volatile("ldmatrix.sync.aligned.m8n8.x4.shared.b16 {%0,%1,%2,%3}, [%4];" \
                 : "=r"(r0), "=r"(r1), "=r"(r2), "=r"(r3) : "r"(addr))
#define LDSM_X4_T(r0, r1, r2, r3, addr)                                          \
    asm volatile("ldmatrix.sync.aligned.m8n8.x4.trans.shared.b16 {%0,%1,%2,%3}, [%4];" \
                 : "=r"(r0), "=r"(r1), "=r"(r2), "=r"(r3) : "r"(addr))

#define MMA16816(d, a, b0, b1)                                                   \
    asm volatile("mma.sync.aligned.m16n8k16.row.col.f32.f16.f16.f32 "            \
                 "{%0,%1,%2,%3}, {%4,%5,%6,%7}, {%8,%9}, {%0,%1,%2,%3};"         \
                 : "+f"((d)[0]), "+f"((d)[1]), "+f"((d)[2]), "+f"((d)[3])        \
                 : "r"((a)[0]), "r"((a)[1]), "r"((a)[2]), "r"((a)[3]),           \
                   "r"(b0), "r"(b1))

// ---------------- convert kernels (split: cap-side / img-side) ----------------
#define CVT_R0H ((M_IMG*IMG_DIM)/8)       // images: 2 float4 per thread
#define CVT_R1H ((IMG_DIM*EMBED)/8)       // W_img:  2 float4 per thread
#define CVT_R2  (M_CAP*80)                // captions pad to 320
#define CVT_R3  (KPAD_TXT*256)            // W_txt pad rows
#define CVT_IMG_THREADS (CVT_R0H + CVT_R1H)
#define CVT_CAP_THREADS (CVT_R2 + CVT_R3)

__global__ void cvt_imgside(const float* __restrict__ images, const float* __restrict__ W_img,
                            __half2* __restrict__ A16I, __half2* __restrict__ W16I)
{
    int idx = blockIdx.x * blockDim.x + threadIdx.x;
    if (idx < CVT_R0H) {
        float4 v0 = ((const float4*)images)[2 * idx];
        float4 v1 = ((const float4*)images)[2 * idx + 1];
        A16I[4 * idx]     = __floats2half2_rn(v0.x, v0.y);
        A16I[4 * idx + 1] = __floats2half2_rn(v0.z, v0.w);
        A16I[4 * idx + 2] = __floats2half2_rn(v1.x, v1.y);
        A16I[4 * idx + 3] = __floats2half2_rn(v1.z, v1.w);
        return;
    }
    idx -= CVT_R0H;
    if (idx < CVT_R1H) {
        float4 v0 = ((const float4*)W_img)[2 * idx];
        float4 v1 = ((const float4*)W_img)[2 * idx + 1];
        W16I[4 * idx]     = __floats2half2_rn(v0.x, v0.y);
        W16I[4 * idx + 1] = __floats2half2_rn(v0.z, v0.w);
        W16I[4 * idx + 2] = __floats2half2_rn(v1.x, v1.y);
        W16I[4 * idx + 3] = __floats2half2_rn(v1.z, v1.w);
    }
}

__global__ void cvt_capside(const float* __restrict__ captions, const float* __restrict__ W_txt,
                            __half2* __restrict__ A16C, __half2* __restrict__ W16T)
{
    int idx = blockIdx.x * blockDim.x + threadIdx.x;
    if (idx < CVT_R2) {
        int row = idx / 80, g = idx - row * 80;
        __half2 h0, h1;
        if (g < 75) {
            float4 v = *(const float4*)(captions + (size_t)row * WORD_DIM + g * 4);
            h0 = __floats2half2_rn(v.x, v.y);
            h1 = __floats2half2_rn(v.z, v.w);
        } else {
            h0 = __floats2half2_rn(0.f, 0.f);
            h1 = h0;
        }
        size_t o = ((size_t)row * KPAD_TXT + g * 4) >> 1;
        A16C[o] = h0; A16C[o + 1] = h1;
        return;
    }
    idx -= CVT_R2;
    if (idx < CVT_R3) {
        int row = idx >> 8, g = idx & 255;
        __half2 h0, h1;
        if (row < WORD_DIM) {
            float4 v = *(const float4*)(W_txt + (size_t)row * EMBED + g * 4);
            h0 = __floats2half2_rn(v.x, v.y);
            h1 = __floats2half2_rn(v.z, v.w);
        } else {
            h0 = __floats2half2_rn(0.f, 0.f);
            h1 = h0;
        }
        size_t o = ((size_t)row * EMBED + g * 4) >> 1;
        W16T[o] = h0; W16T[o + 1] = h1;
    }
}

// ------------- merged fp16 TC GEMM, occ-2 (round-10 champion; blk_offset added) -------
#define GBM 128
#define GBN 128
#define GBK 32
#define STAGES 4
#define STG_A 8192
#define STG_B 8192
#define STG_BYTES (STG_A + STG_B)
#define GEMM_SMEM (STAGES * STG_BYTES)   // 65536

#define IMG_BLKS ((M_IMG / GBM) * (EMBED / GBN))   // 576 (heavy: 64 slabs)
#define CAP_BLKS ((M_CAP / GBM) * (EMBED / GBN))   // 960 (light: 10 slabs)

__device__ __forceinline__ uint32_t aoff(int m, int u) {        // u = k/8 in [0,4)
    int blk  = m >> 1;
    int u128 = ((m & 1) << 2) | u;
    return (uint32_t)((blk << 7) + (((u128 ^ (blk & 7)) << 4)));
}
__device__ __forceinline__ uint32_t boff(int k, int j) {        // j = n/8 in [0,16)
    return (uint32_t)((k << 8) + ((j >> 3) << 7) + (((j & 7) ^ (k & 7)) << 4));
}

__global__ __launch_bounds__(128, 2)
void gemm_all(const __half* __restrict__ Aimg, const __half* __restrict__ Wimg,
              const float* __restrict__ bimg, __half* __restrict__ Cimg,
              const __half* __restrict__ Acap, const __half* __restrict__ Wcap,
              const float* __restrict__ bcap, __half* __restrict__ Ccap,
              int blk_offset)
{
    extern __shared__ char smem[];
    const uint32_t sbase = s2u(smem);
    const int tid  = threadIdx.x;
    const int lane = tid & 31;
    const int wid  = tid >> 5;
    const int wm   = (wid & 1) * 64;
    const int wn   = (wid >> 1) * 64;
    const int N = EMBED;

    const __half *A, *W;
    const float* bias;
    __half* C;
    int K, mb, nb;
    int bx = blockIdx.x + blk_offset;
    if (bx < IMG_BLKS) {
        A = Aimg; W = Wimg; bias = bimg; C = Cimg; K = IMG_DIM;
        mb = bx >> 3; nb = bx & 7;
    } else {
        bx -= IMG_BLKS;
        A = Acap; W = Wcap; bias = bcap; C = Ccap; K = KPAD_TXT;
        mb = bx >> 3; nb = bx & 7;
    }
    const int mbase = mb * GBM;
    const int nbase = nb * GBN;
    const int nk = K / GBK;

    float d[4][8][4];
    #pragma unroll
    for (int i = 0; i < 4; i++)
        #pragma unroll
        for (int j = 0; j < 8; j++)
            #pragma unroll
            for (int q = 0; q < 4; q++) d[i][j][q] = 0.f;

    auto load_slab = [&](int t, int st) {
        const uint32_t sA = sbase + st * STG_BYTES;
        const uint32_t sB = sA + STG_A;
        const int kb = t * GBK;
        #pragma unroll
        for (int i = 0; i < 4; i++) {
            int c = tid + i * 128;
            int m = c >> 2, u = c & 3;
            cp16(sA + aoff(m, u), A + (size_t)(mbase + m) * K + kb + u * 8);
        }
        #pragma unroll
        for (int i = 0; i < 4; i++) {
            int c = tid + i * 128;
            int k = c >> 4, j = c & 15;
            cp16(sB + boff(k, j), W + (size_t)(kb + k) * N + nbase + j * 8);
        }
        CP_COMMIT();
    };

    load_slab(0, 0);
    load_slab(1, 1);
    load_slab(2, 2);

    for (int s = 0; s < nk; s++) {
        const int rem = nk - 1 - s;
        if (rem >= 2)      asm volatile("cp.async.wait_group 2;" ::: "memory");
        else if (rem == 1) asm volatile("cp.async.wait_group 1;" ::: "memory");
        else               asm volatile("cp.async.wait_group 0;" ::: "memory");
        __syncthreads();
        if (s + 3 < nk) load_slab(s + 3, (s + 3) & 3);

        const uint32_t sA = sbase + (s & 3) * STG_BYTES;
        const uint32_t sB = sA + STG_A;
        #pragma unroll
        for (int ks = 0; ks < 2; ks++) {
            uint32_t a[4][4], bb[4][4];
            #pragma unroll
            for (int mi = 0; mi < 4; mi++) {
                int m = wm + mi * 16 + (lane & 15);
                int u = ks * 2 + (lane >> 4);
                LDSM_X4(a[mi][0], a[mi][1], a[mi][2], a[mi][3], sA + aoff(m, u));
            }
            #pragma unroll
            for (int p = 0; p < 4; p++) {
                int k = ks * 16 + (lane & 7) + ((lane >> 3) & 1) * 8;
                int j = ((wn + p * 16) >> 3) + (lane >> 4);
                LDSM_X4_T(bb[p][0], bb[p][1], bb[p][2], bb[p][3], sB + boff(k, j));
            }
            #pragma unroll
            for (int mi = 0; mi < 4; mi++)
                #pragma unroll
                for (int nj = 0; nj < 8; nj++)
                    MMA16816(d[mi][nj], a[mi], bb[nj >> 1][(nj & 1) * 2],
                                               bb[nj >> 1][(nj & 1) * 2 + 1]);
        }
    }

    #pragma unroll
    for (int mi = 0; mi < 4; mi++) {
        int r0 = mbase + wm + mi * 16 + (lane >> 2);
        #pragma unroll
        for (int nj = 0; nj < 8; nj++) {
            int cc = nbase + wn + nj * 8 + ((lane & 3) << 1);
            float2 bv = *(const float2*)(bias + cc);
            *(__half2*)(C + (size_t)r0 * N + cc) =
                __floats2half2_rn(d[mi][nj][0] + bv.x, d[mi][nj][1] + bv.y);
            *(__half2*)(C + (size_t)(r0 + 8) * N + cc) =
                __floats2half2_rn(d[mi][nj][2] + bv.x, d[mi][nj][3] + bv.y);
        }
    }
}

// ------- fused sim + gram + l2norm + softmax + cosine + mean (round-7 config) -------
#define SA_THREADS 192
#define SA_ROWS 112
#define SA_ROWB 128
#define SA_BUF (SA_ROWS * SA_ROWB)
#define SA_NSLAB 16
#define SSTRIDE 50
#define OFF_BUF  0
#define OFF_SS   (2 * SA_BUF)
#define OFF_SINV (OFF_SS + 96 * SSTRIDE * 4)
#define OFF_SW   (OFF_SINV + 112 * 4)
#define OFF_WSUM (OFF_SW + 6 * 40 * 4)
#define SA_SMEM  (OFF_WSUM + 32)

__device__ __forceinline__ uint32_t soff_sa(int r, int c) {
    return (uint32_t)(r * SA_ROWB + (((c ^ (r & 7)) << 4)));
}

__global__ __launch_bounds__(SA_THREADS, 1)
void simattn(const __half* __restrict__ cap, const __half* __restrict__ img,
             const int* __restrict__ lens, float* __restrict__ out)
{
    extern __shared__ char smem[];
    const uint32_t sbase = s2u(smem);
    float* SS   = (float*)(smem + OFF_SS);
    float* sinv = (float*)(smem + OFF_SINV);
    float* sW   = (float*)(smem + OFF_SW);
    float* wsum = (float*)(smem + OFF_WSUM);

    const int b    = blockIdx.x;
    const int tid  = threadIdx.x;
    const int warp = tid >> 5, lane = tid & 31;

    const __half* capb = cap + (size_t)b * NWORD * EMBED;
    const __half* imgb = img + (size_t)b * NREG  * EMBED;

    const int myrow = tid >> 1;
    const int c0    = (tid & 1) * 4;
    const __half* growp = (myrow < NWORD) ? (capb + (size_t)myrow * EMBED)
                                          : (imgb + (size_t)(myrow - NWORD) * EMBED);

    for (int idx = tid; idx < 2 * 16 * 8; idx += SA_THREADS) {
        int bf = idx >> 7, rem = idx & 127;
        int r = 96 + (rem >> 3), c = rem & 7;
        *(uint4*)(smem + OFF_BUF + bf * SA_BUF + soff_sa(r, c)) = make_uint4(0, 0, 0, 0);
    }

    auto load_slab = [&](int s, int bf) {
        const uint32_t sb = sbase + OFF_BUF + bf * SA_BUF;
        const __half* gp = growp + s * 64;
        #pragma unroll
        for (int i = 0; i < 4; i++)
            cp16(sb + soff_sa(myrow, c0 + i), gp + (c0 + i) * 8);
        CP_COMMIT();
    };

    float d[6][4];
    #pragma unroll
    for (int j = 0; j < 6; j++)
        #pragma unroll
        for (int q = 0; q < 4; q++) d[j][q] = 0.f;
    float sq = 0.f;

    load_slab(0, 0);

    for (int s = 0; s < SA_NSLAB; s++) {
        if (s + 1 < SA_NSLAB) {
            load_slab(s + 1, (s + 1) & 1);
            asm volatile("cp.async.wait_group 1;" ::: "memory");
        } else {
            asm volatile("cp.async.wait_group 0;" ::: "memory");
        }
        __syncthreads();
        const int bf = s & 1;
        const uint32_t sb = sbase + OFF_BUF + bf * SA_BUF;

        #pragma unroll
        for (int i = 0; i < 4; i++) {
            uint4 v = *(uint4*)(smem + OFF_BUF + bf * SA_BUF + soff_sa(myrow, c0 + i));
            uint32_t w[4] = {v.x, v.y, v.z, v.w};
            #pragma unroll
            for (int q = 0; q < 4; q++) {
                float2 f = __half22float2(*(__half2*)&w[q]);
                sq += f.x * f.x + f.y * f.y;
            }
        }

        #pragma unroll
        for (int ks = 0; ks < 4; ks++) {
            const int ch = ks * 2 + (lane >> 4);
            uint32_t a[4];
            LDSM_X4(a[0], a[1], a[2], a[3], sb + soff_sa(warp * 16 + (lane & 15), ch));
            #pragma unroll
            for (int jb = 0; jb < 3; jb++) {
                uint32_t bb[4];
                LDSM_X4(bb[0], bb[1], bb[2], bb[3],
                        sb + soff_sa(60 + jb * 16 + (lane & 15), ch));
                MMA16816(d[2 * jb],     a, bb[0], bb[2]);
                MMA16816(d[2 * jb + 1], a, bb[1], bb[3]);
            }
        }
        __syncthreads();
    }

    float tot = sq + __shfl_xor_sync(0xffffffffu, sq, 1);
    if ((tid & 1) == 0) sinv[myrow] = tot;
    __syncthreads();
    if (tid < 112) sinv[tid] = (tid < 96) ? rsqrtf(sinv[tid] + 1e-12f) : 1.0f;
    __syncthreads();

    {
        const int fr = lane >> 2;
        const int fc = (lane & 3) << 1;
        #pragma unroll
        for (int jj = 0; jj < 6; jj++) {
            int col = jj * 8 + fc;
            float cn0 = sinv[60 + col], cn1 = sinv[60 + col + 1];
            int r0 = warp * 16 + fr;
            float rn0 = sinv[r0], rn1 = sinv[r0 + 8];
            SS[r0 * SSTRIDE + col]            = d[jj][0] * rn0 * cn0;
            SS[r0 * SSTRIDE + col + 1]        = d[jj][1] * rn0 * cn1;
            SS[(r0 + 8) * SSTRIDE + col]      = d[jj][2] * rn1 * cn0;
            SS[(r0 + 8) * SSTRIDE + col + 1]  = d[jj][3] * rn1 * cn1;
        }
    }
    __syncthreads();

    const int len = lens[b];
    float partial = 0.f;

    for (int l = warp; l < len; l += 6) {
        const float* sr = SS + l * SSTRIDE;
        float s0 = sr[lane];
        float s1 = (lane < 4) ? sr[lane + 32] : -1e30f;
        float m = fmaxf(s0, s1);
        #pragma unroll
        for (int o = 16; o > 0; o >>= 1) m = fmaxf(m, __shfl_xor_sync(0xffffffffu, m, o));

        float e0 = __expf(LAMBDA_SM * (s0 - m));
        float e1 = (lane < 4) ? __expf(LAMBDA_SM * (s1 - m)) : 0.f;
        float Z = e0 + e1;
        #pragma unroll
        for (int o = 16; o > 0; o >>= 1) Z += __shfl_xor_sync(0xffffffffu, Z, o);
        float inv = 1.f / Z;
        float w0 = e0 * inv;
        float w1 = e1 * inv;

        sW[warp * 40 + lane] = w0;
        if (lane < 4) sW[warp * 40 + lane + 32] = w1;
        __syncwarp();

        float num = w0 * s0 + ((lane < 4) ? w1 * s1 : 0.f);
        #pragma unroll
        for (int o = 16; o > 0; o >>= 1) num += __shfl_xor_sync(0xffffffffu, num, o);

        float t0 = 0.f;
        const float* gr0 = SS + (60 + lane) * SSTRIDE;
        #pragma unroll
        for (int rp = 0; rp < NREG; rp++) t0 += sW[warp * 40 + rp] * gr0[rp];
        float den2 = w0 * t0;
        if (lane < 4) {
            float t1 = 0.f;
            const float* gr1 = SS + (60 + lane + 32) * SSTRIDE;
            #pragma unroll
            for (int rp = 0; rp < NREG; rp++) t1 += sW[warp * 40 + rp] * gr1[rp];
            den2 += w1 * t1;
        }
        #pragma unroll
        for (int o = 16; o > 0; o >>= 1) den2 += __shfl_xor_sync(0xffffffffu, den2, o);

        float den = fmaxf(sqrtf(den2), 1e-8f);
        partial += num / den;
        __syncwarp();
    }

    if (lane == 0) wsum[warp] = partial;
    __syncthreads();
    if (tid == 0) {
        float t = 0.f;
        #pragma unroll
        for (int w = 0; w < 6; w++) t += wsum[w];
        out[b] = t / (float)len;
    }
}

// ---------------- launcher: fork-join overlap of cvt_img with gemm_cap ----------------
extern "C" void kernel_launch(void* const* d_in, const int* in_sizes, int n_in,
                              void* d_out, int out_size)
{
    const float* images      = (const float*)d_in[0];
    const float* captions    = (const float*)d_in[1];
    const int*   cap_lengths = (const int*)  d_in[2];
    const float* W_img       = (const float*)d_in[3];
    const float* b_img       = (const float*)d_in[4];
    const float* W_txt       = (const float*)d_in[5];
    const float* b_txt       = (const float*)d_in[6];
    float* out = (float*)d_out;

    __half *img_embs, *cap_embs, *A16I, *A16C, *W16I, *W16T;
    cudaGetSymbolAddress((void**)&img_embs, g_img_embs);
    cudaGetSymbolAddress((void**)&cap_embs, g_cap_embs);
    cudaGetSymbolAddress((void**)&A16I, g_A16_img);
    cudaGetSymbolAddress((void**)&A16C, g_A16_cap);
    cudaGetSymbolAddress((void**)&W16I, g_W16_img);
    cudaGetSymbolAddress((void**)&W16T, g_W16_txt);

    cudaFuncSetAttribute(gemm_all, cudaFuncAttributeMaxDynamicSharedMemorySize, GEMM_SMEM);
    cudaFuncSetAttribute(simattn,  cudaFuncAttributeMaxDynamicSharedMemorySize, SA_SMEM);

    // persistent side stream + events (created once, outside capture; no device allocs)
    static cudaStream_t s2 = nullptr;
    static cudaEvent_t evFork = nullptr, evImg = nullptr;
    if (s2 == nullptr) {
        cudaStreamCreateWithFlags(&s2, cudaStreamNonBlocking);
        cudaEventCreateWithFlags(&evFork, cudaEventDisableTiming);
        cudaEventCreateWithFlags(&evImg, cudaEventDisableTiming);
    }

    // fork: img-side convert on s2, concurrent with cap-side convert + cap GEMM
    cudaEventRecord(evFork, 0);
    cudaStreamWaitEvent(s2, evFork, 0);
    cvt_imgside<<<(CVT_IMG_THREADS + 255) / 256, 256, 0, s2>>>(
        images, W_img, (__half2*)A16I, (__half2*)W16I);
    cudaEventRecord(evImg, s2);

    cvt_capside<<<(CVT_CAP_THREADS + 255) / 256, 256>>>(
        captions, W_txt, (__half2*)A16C, (__half2*)W16T);

    // cap GEMM (blocks [IMG_BLKS, IMG_BLKS+CAP_BLKS)) — overlaps cvt_imgside
    gemm_all<<<CAP_BLKS, 128, GEMM_SMEM>>>(
        A16I, W16I, b_img, img_embs,
        A16C, W16T, b_txt, cap_embs, IMG_BLKS);

    // join: img GEMM needs A16I/W16I
    cudaStreamWaitEvent(0, evImg, 0);
    gemm_all<<<IMG_BLKS, 128, GEMM_SMEM>>>(
        A16I, W16I, b_img, img_embs,
        A16C, W16T, b_txt, cap_embs, 0);

    // fused sim + gram + norm + softmax + cosine + mean
    simattn<<<BATCH, SA_THREADS, SA_SMEM>>>(cap_embs, img_embs, cap_lengths, out);
}

// round 13
// speedup vs baseline: 1.0640x; 1.0640x over previous
#include <cuda_runtime.h>
#include <cuda_fp16.h>
#include <math.h>
#include <stdint.h>

// ---------------- problem constants ----------------
#define BATCH    256
#define NREG     36
#define NWORD    60
#define IMG_DIM  2048
#define WORD_DIM 300
#define KPAD_TXT 320
#define EMBED    1024
#define LAMBDA_SM 9.0f
#define M_IMG (BATCH*NREG)     // 9216
#define M_CAP (BATCH*NWORD)    // 15360

// ---------------- scratch (device globals; no allocation allowed) ----------------
__device__ __align__(256) __half g_img_embs[M_IMG * EMBED];
__device__ __align__(256) __half g_cap_embs[M_CAP * EMBED];

__device__ __align__(256) __half g_A16_img[M_IMG * IMG_DIM];
__device__ __align__(256) __half g_A16_cap[M_CAP * KPAD_TXT];
__device__ __align__(256) __half g_W16_img[IMG_DIM * EMBED];
__device__ __align__(256) __half g_W16_txt[KPAD_TXT * EMBED];

// ---------------- PTX helpers (sm_80-level only) ----------------
__device__ __forceinline__ uint32_t s2u(const void* p) {
    uint32_t a;
    asm("{ .reg .u64 t; cvta.to.shared.u64 t, %1; cvt.u32.u64 %0, t; }" : "=r"(a) : "l"(p));
    return a;
}
__device__ __forceinline__ void cp16(uint32_t s, const void* g) {
    asm volatile("cp.async.cg.shared.global [%0], [%1], 16;" :: "r"(s), "l"(g));
}
#define CP_COMMIT() asm volatile("cp.async.commit_group;" ::: "memory")

#define LDSM_X4(r0, r1, r2, r3, addr)                                            \
    asm volatile("ldmatrix.sync.aligned.m8n8.x4.shared.b16 {%0,%1,%2,%3}, [%4];" \
                 : "=r"(r0), "=r"(r1), "=r"(r2), "=r"(r3) : "r"(addr))
#define LDSM_X4_T(r0, r1, r2, r3, addr)                                          \
    asm volatile("ldmatrix.sync.aligned.m8n8.x4.trans.shared.b16 {%0,%1,%2,%3}, [%4];" \
                 : "=r"(r0), "=r"(r1), "=r"(r2), "=r"(r3) : "r"(addr))

#define MMA16816(d, a, b0, b1)                                                   \
    asm volatile("mma.sync.aligned.m16n8k16.row.col.f32.f16.f16.f32 "            \
                 "{%0,%1,%2,%3}, {%4,%5,%6,%7}, {%8,%9}, {%0,%1,%2,%3};"         \
                 : "+f"((d)[0]), "+f"((d)[1]), "+f"((d)[2]), "+f"((d)[3])        \
                 : "r"((a)[0]), "r"((a)[1]), "r"((a)[2]), "r"((a)[3]),           \
                   "r"(b0), "r"(b1))

// ---------------- merged convert kernel (8 floats/thread on big regions) ----
#define CVT_R0H ((M_IMG*IMG_DIM)/8)
#define CVT_R1H ((IMG_DIM*EMBED)/8)
#define CVT_R2  (M_CAP*80)
#define CVT_R3  (KPAD_TXT*256)
#define CVT_THREADS (CVT_R0H + CVT_R1H + CVT_R2 + CVT_R3)

__global__ void cvt_all(const float* __restrict__ images, const float* __restrict__ W_img,
                        const float* __restrict__ captions, const float* __restrict__ W_txt,
                        __half2* __restrict__ A16I, __half2* __restrict__ W16I,
                        __half2* __restrict__ A16C, __half2* __restrict__ W16T)
{
    int idx = blockIdx.x * blockDim.x + threadIdx.x;
    if (idx < CVT_R0H) {
        float4 v0 = ((const float4*)images)[2 * idx];
        float4 v1 = ((const float4*)images)[2 * idx + 1];
        A16I[4 * idx]     = __floats2half2_rn(v0.x, v0.y);
        A16I[4 * idx + 1] = __floats2half2_rn(v0.z, v0.w);
        A16I[4 * idx + 2] = __floats2half2_rn(v1.x, v1.y);
        A16I[4 * idx + 3] = __floats2half2_rn(v1.z, v1.w);
        return;
    }
    idx -= CVT_R0H;
    if (idx < CVT_R1H) {
        float4 v0 = ((const float4*)W_img)[2 * idx];
        float4 v1 = ((const float4*)W_img)[2 * idx + 1];
        W16I[4 * idx]     = __floats2half2_rn(v0.x, v0.y);
        W16I[4 * idx + 1] = __floats2half2_rn(v0.z, v0.w);
        W16I[4 * idx + 2] = __floats2half2_rn(v1.x, v1.y);
        W16I[4 * idx + 3] = __floats2half2_rn(v1.z, v1.w);
        return;
    }
    idx -= CVT_R1H;
    if (idx < CVT_R2) {
        int row = idx / 80, g = idx - row * 80;
        __half2 h0, h1;
        if (g < 75) {
            float4 v = *(const float4*)(captions + (size_t)row * WORD_DIM + g * 4);
            h0 = __floats2half2_rn(v.x, v.y);
            h1 = __floats2half2_rn(v.z, v.w);
        } else {
            h0 = __floats2half2_rn(0.f, 0.f);
            h1 = h0;
        }
        size_t o = ((size_t)row * KPAD_TXT + g * 4) >> 1;
        A16C[o] = h0; A16C[o + 1] = h1;
        return;
    }
    idx -= CVT_R2;
    if (idx < CVT_R3) {
        int row = idx >> 8, g = idx & 255;
        __half2 h0, h1;
        if (row < WORD_DIM) {
            float4 v = *(const float4*)(W_txt + (size_t)row * EMBED + g * 4);
            h0 = __floats2half2_rn(v.x, v.y);
            h1 = __floats2half2_rn(v.z, v.w);
        } else {
            h0 = __floats2half2_rn(0.f, 0.f);
            h1 = h0;
        }
        size_t o = ((size_t)row * EMBED + g * 4) >> 1;
        W16T[o] = h0; W16T[o + 1] = h1;
    }
}

// ------------- merged fp16 TC GEMM, occ-2 (round-10 champion, frozen) -------
#define GBM 128
#define GBN 128
#define GBK 32
#define STAGES 4
#define STG_A 8192
#define STG_B 8192
#define STG_BYTES (STG_A + STG_B)
#define GEMM_SMEM (STAGES * STG_BYTES)   // 65536

#define IMG_BLKS ((M_IMG / GBM) * (EMBED / GBN))   // 576 (heavy: 64 slabs)
#define CAP_BLKS ((M_CAP / GBM) * (EMBED / GBN))   // 960 (light: 10 slabs)
#define TOT_BLKS (IMG_BLKS + CAP_BLKS)             // 1536

__device__ __forceinline__ uint32_t aoff(int m, int u) {        // u = k/8 in [0,4)
    int blk  = m >> 1;
    int u128 = ((m & 1) << 2) | u;
    return (uint32_t)((blk << 7) + (((u128 ^ (blk & 7)) << 4)));
}
__device__ __forceinline__ uint32_t boff(int k, int j) {        // j = n/8 in [0,16)
    return (uint32_t)((k << 8) + ((j >> 3) << 7) + (((j & 7) ^ (k & 7)) << 4));
}

__global__ __launch_bounds__(128, 2)
void gemm_all(const __half* __restrict__ Aimg, const __half* __restrict__ Wimg,
              const float* __restrict__ bimg, __half* __restrict__ Cimg,
              const __half* __restrict__ Acap, const __half* __restrict__ Wcap,
              const float* __restrict__ bcap, __half* __restrict__ Ccap)
{
    extern __shared__ char smem[];
    const uint32_t sbase = s2u(smem);
    const int tid  = threadIdx.x;
    const int lane = tid & 31;
    const int wid  = tid >> 5;
    const int wm   = (wid & 1) * 64;
    const int wn   = (wid >> 1) * 64;
    const int N = EMBED;

    const __half *A, *W;
    const float* bias;
    __half* C;
    int K, mb, nb;
    int bx = blockIdx.x;
    if (bx < IMG_BLKS) {
        A = Aimg; W = Wimg; bias = bimg; C = Cimg; K = IMG_DIM;
        mb = bx >> 3; nb = bx & 7;
    } else {
        bx -= IMG_BLKS;
        A = Acap; W = Wcap; bias = bcap; C = Ccap; K = KPAD_TXT;
        mb = bx >> 3; nb = bx & 7;
    }
    const int mbase = mb * GBM;
    const int nbase = nb * GBN;
    const int nk = K / GBK;

    float d[4][8][4];
    #pragma unroll
    for (int i = 0; i < 4; i++)
        #pragma unroll
        for (int j = 0; j < 8; j++)
            #pragma unroll
            for (int q = 0; q < 4; q++) d[i][j][q] = 0.f;

    auto load_slab = [&](int t, int st) {
        const uint32_t sA = sbase + st * STG_BYTES;
        const uint32_t sB = sA + STG_A;
        const int kb = t * GBK;
        #pragma unroll
        for (int i = 0; i < 4; i++) {
            int c = tid + i * 128;
            int m = c >> 2, u = c & 3;
            cp16(sA + aoff(m, u), A + (size_t)(mbase + m) * K + kb + u * 8);
        }
        #pragma unroll
        for (int i = 0; i < 4; i++) {
            int c = tid + i * 128;
            int k = c >> 4, j = c & 15;
            cp16(sB + boff(k, j), W + (size_t)(kb + k) * N + nbase + j * 8);
        }
        CP_COMMIT();
    };

    load_slab(0, 0);
    load_slab(1, 1);
    load_slab(2, 2);

    for (int s = 0; s < nk; s++) {
        const int rem = nk - 1 - s;
        if (rem >= 2)      asm volatile("cp.async.wait_group 2;" ::: "memory");
        else if (rem == 1) asm volatile("cp.async.wait_group 1;" ::: "memory");
        else               asm volatile("cp.async.wait_group 0;" ::: "memory");
        __syncthreads();
        if (s + 3 < nk) load_slab(s + 3, (s + 3) & 3);

        const uint32_t sA = sbase + (s & 3) * STG_BYTES;
        const uint32_t sB = sA + STG_A;
        #pragma unroll
        for (int ks = 0; ks < 2; ks++) {
            uint32_t a[4][4], bb[4][4];
            #pragma unroll
            for (int mi = 0; mi < 4; mi++) {
                int m = wm + mi * 16 + (lane & 15);
                int u = ks * 2 + (lane >> 4);
                LDSM_X4(a[mi][0], a[mi][1], a[mi][2], a[mi][3], sA + aoff(m, u));
            }
            #pragma unroll
            for (int p = 0; p < 4; p++) {
                int k = ks * 16 + (lane & 7) + ((lane >> 3) & 1) * 8;
                int j = ((wn + p * 16) >> 3) + (lane >> 4);
                LDSM_X4_T(bb[p][0], bb[p][1], bb[p][2], bb[p][3], sB + boff(k, j));
            }
            #pragma unroll
            for (int mi = 0; mi < 4; mi++)
                #pragma unroll
                for (int nj = 0; nj < 8; nj++)
                    MMA16816(d[mi][nj], a[mi], bb[nj >> 1][(nj & 1) * 2],
                                               bb[nj >> 1][(nj & 1) * 2 + 1]);
        }
    }

    #pragma unroll
    for (int mi = 0; mi < 4; mi++) {
        int r0 = mbase + wm + mi * 16 + (lane >> 2);
        #pragma unroll
        for (int nj = 0; nj < 8; nj++) {
            int cc = nbase + wn + nj * 8 + ((lane & 3) << 1);
            float2 bv = *(const float2*)(bias + cc);
            *(__half2*)(C + (size_t)r0 * N + cc) =
                __floats2half2_rn(d[mi][nj][0] + bv.x, d[mi][nj][1] + bv.y);
            *(__half2*)(C + (size_t)(r0 + 8) * N + cc) =
                __floats2half2_rn(d[mi][nj][2] + bv.x, d[mi][nj][3] + bv.y);
        }
    }
}

// ------- fused sim + gram + l2norm + softmax + cosine + mean -------
// Changes vs round 7: depth-2 cp.async prefetch (3 buffers) and row sumsq
// computed from MMA A-fragments (deletes the smem re-read pass).
#define SA_THREADS 192
#define SA_ROWS 112
#define SA_ROWB 128
#define SA_BUF (SA_ROWS * SA_ROWB)     // 14336
#define SA_NSLAB 16
#define SSTRIDE 50
#define OFF_BUF  0
#define OFF_SS   (3 * SA_BUF)                    // 43008
#define OFF_SINV (OFF_SS + 96 * SSTRIDE * 4)     // 62208
#define OFF_SW   (OFF_SINV + 112 * 4)            // 62656
#define OFF_WSUM (OFF_SW + 6 * 40 * 4)           // 63616
#define SA_SMEM  (OFF_WSUM + 32)                 // 63648

__device__ __forceinline__ uint32_t soff_sa(int r, int c) {
    return (uint32_t)(r * SA_ROWB + (((c ^ (r & 7)) << 4)));
}

__global__ __launch_bounds__(SA_THREADS, 1)
void simattn(const __half* __restrict__ cap, const __half* __restrict__ img,
             const int* __restrict__ lens, float* __restrict__ out)
{
    extern __shared__ char smem[];
    const uint32_t sbase = s2u(smem);
    float* SS   = (float*)(smem + OFF_SS);
    float* sinv = (float*)(smem + OFF_SINV);
    float* sW   = (float*)(smem + OFF_SW);
    float* wsum = (float*)(smem + OFF_WSUM);

    const int b    = blockIdx.x;
    const int tid  = threadIdx.x;
    const int warp = tid >> 5, lane = tid & 31;

    const __half* capb = cap + (size_t)b * NWORD * EMBED;
    const __half* imgb = img + (size_t)b * NREG  * EMBED;

    const int myrow = tid >> 1;
    const int c0    = (tid & 1) * 4;
    const __half* growp = (myrow < NWORD) ? (capb + (size_t)myrow * EMBED)
                                          : (imgb + (size_t)(myrow - NWORD) * EMBED);

    // zero n-padding rows (96..111) of all 3 buffers
    for (int idx = tid; idx < 3 * 16 * 8; idx += SA_THREADS) {
        int bf = idx >> 7, rem = idx & 127;
        int r = 96 + (rem >> 3), c = rem & 7;
        *(uint4*)(smem + OFF_BUF + bf * SA_BUF + soff_sa(r, c)) = make_uint4(0, 0, 0, 0);
    }

    auto load_slab = [&](int s, int bf) {
        const uint32_t sb = sbase + OFF_BUF + bf * SA_BUF;
        const __half* gp = growp + s * 64;
        #pragma unroll
        for (int i = 0; i < 4; i++)
            cp16(sb + soff_sa(myrow, c0 + i), gp + (c0 + i) * 8);
        CP_COMMIT();
    };

    float d[6][4];
    #pragma unroll
    for (int j = 0; j < 6; j++)
        #pragma unroll
        for (int q = 0; q < 4; q++) d[j][q] = 0.f;
    float sqA = 0.f, sqB = 0.f;    // rows warp*16+(lane>>2) and +8

    load_slab(0, 0);
    load_slab(1, 1);

    for (int s = 0; s < SA_NSLAB; s++) {
        if (s + 2 < SA_NSLAB) load_slab(s + 2, (s + 2) % 3);
        const int rem = SA_NSLAB - 1 - s;
        if (rem >= 2)      asm volatile("cp.async.wait_group 2;" ::: "memory");
        else if (rem == 1) asm volatile("cp.async.wait_group 1;" ::: "memory");
        else               asm volatile("cp.async.wait_group 0;" ::: "memory");
        __syncthreads();
        const uint32_t sb = sbase + OFF_BUF + (s % 3) * SA_BUF;

        #pragma unroll
        for (int ks = 0; ks < 4; ks++) {
            const int ch = ks * 2 + (lane >> 4);
            uint32_t a[4];
            LDSM_X4(a[0], a[1], a[2], a[3], sb + soff_sa(warp * 16 + (lane & 15), ch));
            // row sum-squares from fragments: regs 0,2 -> row fr; regs 1,3 -> row fr+8
            {
                float2 f0 = __half22float2(*(__half2*)&a[0]);
                float2 f2 = __half22float2(*(__half2*)&a[2]);
                sqA = fmaf(f0.x, f0.x, sqA); sqA = fmaf(f0.y, f0.y, sqA);
                sqA = fmaf(f2.x, f2.x, sqA); sqA = fmaf(f2.y, f2.y, sqA);
                float2 f1 = __half22float2(*(__half2*)&a[1]);
                float2 f3 = __half22float2(*(__half2*)&a[3]);
                sqB = fmaf(f1.x, f1.x, sqB); sqB = fmaf(f1.y, f1.y, sqB);
                sqB = fmaf(f3.x, f3.x, sqB); sqB = fmaf(f3.y, f3.y, sqB);
            }
            #pragma unroll
            for (int jb = 0; jb < 3; jb++) {
                uint32_t bb[4];
                LDSM_X4(bb[0], bb[1], bb[2], bb[3],
                        sb + soff_sa(60 + jb * 16 + (lane & 15), ch));
                MMA16816(d[2 * jb],     a, bb[0], bb[2]);
                MMA16816(d[2 * jb + 1], a, bb[1], bb[3]);
            }
        }
        __syncthreads();
    }

    // reduce sumsq over the 4 lanes sharing a row (k-groups)
    #pragma unroll
    for (int o = 1; o <= 2; o <<= 1) {
        sqA += __shfl_xor_sync(0xffffffffu, sqA, o);
        sqB += __shfl_xor_sync(0xffffffffu, sqB, o);
    }
    if ((lane & 3) == 0) {
        int fr = lane >> 2;
        sinv[warp * 16 + fr]     = sqA;
        sinv[warp * 16 + fr + 8] = sqB;
    }
    __syncthreads();
    if (tid < 112) sinv[tid] = (tid < 96) ? rsqrtf(sinv[tid] + 1e-12f) : 1.0f;
    __syncthreads();

    {
        const int fr = lane >> 2;
        const int fc = (lane & 3) << 1;
        #pragma unroll
        for (int jj = 0; jj < 6; jj++) {
            int col = jj * 8 + fc;
            float cn0 = sinv[60 + col], cn1 = sinv[60 + col + 1];
            int r0 = warp * 16 + fr;
            float rn0 = sinv[r0], rn1 = sinv[r0 + 8];
            SS[r0 * SSTRIDE + col]            = d[jj][0] * rn0 * cn0;
            SS[r0 * SSTRIDE + col + 1]        = d[jj][1] * rn0 * cn1;
            SS[(r0 + 8) * SSTRIDE + col]      = d[jj][2] * rn1 * cn0;
            SS[(r0 + 8) * SSTRIDE + col + 1]  = d[jj][3] * rn1 * cn1;
        }
    }
    __syncthreads();

    const int len = lens[b];
    float partial = 0.f;

    for (int l = warp; l < len; l += 6) {
        const float* sr = SS + l * SSTRIDE;
        float s0 = sr[lane];
        float s1 = (lane < 4) ? sr[lane + 32] : -1e30f;
        float m = fmaxf(s0, s1);
        #pragma unroll
        for (int o = 16; o > 0; o >>= 1) m = fmaxf(m, __shfl_xor_sync(0xffffffffu, m, o));

        float e0 = __expf(LAMBDA_SM * (s0 - m));
        float e1 = (lane < 4) ? __expf(LAMBDA_SM * (s1 - m)) : 0.f;
        float Z = e0 + e1;
        #pragma unroll
        for (int o = 16; o > 0; o >>= 1) Z += __shfl_xor_sync(0xffffffffu, Z, o);
        float inv = 1.f / Z;
        float w0 = e0 * inv;
        float w1 = e1 * inv;

        sW[warp * 40 + lane] = w0;
        if (lane < 4) sW[warp * 40 + lane + 32] = w1;
        __syncwarp();

        float num = w0 * s0 + ((lane < 4) ? w1 * s1 : 0.f);
        #pragma unroll
        for (int o = 16; o > 0; o >>= 1) num += __shfl_xor_sync(0xffffffffu, num, o);

        float t0 = 0.f;
        const float* gr0 = SS + (60 + lane) * SSTRIDE;
        #pragma unroll
        for (int rp = 0; rp < NREG; rp++) t0 += sW[warp * 40 + rp] * gr0[rp];
        float den2 = w0 * t0;
        if (lane < 4) {
            float t1 = 0.f;
            const float* gr1 = SS + (60 + lane + 32) * SSTRIDE;
            #pragma unroll
            for (int rp = 0; rp < NREG; rp++) t1 += sW[warp * 40 + rp] * gr1[rp];
            den2 += w1 * t1;
        }
        #pragma unroll
        for (int o = 16; o > 0; o >>= 1) den2 += __shfl_xor_sync(0xffffffffu, den2, o);

        float den = fmaxf(sqrtf(den2), 1e-8f);
        partial += num / den;
        __syncwarp();
    }

    if (lane == 0) wsum[warp] = partial;
    __syncthreads();
    if (tid == 0) {
        float t = 0.f;
        #pragma unroll
        for (int w = 0; w < 6; w++) t += wsum[w];
        out[b] = t / (float)len;
    }
}

// ---------------- launcher (round-10 serial structure) ----------------
extern "C" void kernel_launch(void* const* d_in, const int* in_sizes, int n_in,
                              void* d_out, int out_size)
{
    const float* images      = (const float*)d_in[0];
    const float* captions    = (const float*)d_in[1];
    const int*   cap_lengths = (const int*)  d_in[2];
    const float* W_img       = (const float*)d_in[3];
    const float* b_img       = (const float*)d_in[4];
    const float* W_txt       = (const float*)d_in[5];
    const float* b_txt       = (const float*)d_in[6];
    float* out = (float*)d_out;

    __half *img_embs, *cap_embs, *A16I, *A16C, *W16I, *W16T;
    cudaGetSymbolAddress((void**)&img_embs, g_img_embs);
    cudaGetSymbolAddress((void**)&cap_embs, g_cap_embs);
    cudaGetSymbolAddress((void**)&A16I, g_A16_img);
    cudaGetSymbolAddress((void**)&A16C, g_A16_cap);
    cudaGetSymbolAddress((void**)&W16I, g_W16_img);
    cudaGetSymbolAddress((void**)&W16T, g_W16_txt);

    cudaFuncSetAttribute(gemm_all, cudaFuncAttributeMaxDynamicSharedMemorySize, GEMM_SMEM);
    cudaFuncSetAttribute(simattn,  cudaFuncAttributeMaxDynamicSharedMemorySize, SA_SMEM);

    // merged convert (8 floats/thread on the big regions)
    cvt_all<<<(CVT_THREADS + 255) / 256, 256>>>(images, W_img, captions, W_txt,
                                                (__half2*)A16I, (__half2*)W16I,
                                                (__half2*)A16C, (__half2*)W16T);

    // merged GEMM, occupancy 2 (champion config; img tiles first)
    gemm_all<<<TOT_BLKS, 128, GEMM_SMEM>>>(
        A16I, W16I, b_img, img_embs,
        A16C, W16T, b_txt, cap_embs);

    // fused sim + gram + norm + softmax + cosine + mean (depth-2, fragment sumsq)
    simattn<<<BATCH, SA_THREADS, SA_SMEM>>>(cap_embs, img_embs, cap_lengths, out);
}